// round 2
// baseline (speedup 1.0000x reference)
#include <cuda_runtime.h>
#include <cstddef>
#include <cstdint>
#include <math.h>

// CTC batch cost (Keras semantics): B=256, T=512, V=256, L=64, blank=V-1
// loss[b] = -log P(y_true[b] | y_pred[b]), logp = log(y_pred + 1e-7)
//
// Linear-domain forward DP with PER-LANE power-of-2 scaling (exact integer
// exponent offsets, renormalized every 8 steps). One warp per batch element.
// Lane j owns states:
//   La = alpha[label 2j]   (s=4j+1)
//   Lb = alpha[label 2j+1] (s=4j+3)
//   Ba = alpha[blank 2j]   (s=4j)
//   Bb = alpha[blank 2j+1] (s=4j+2)
//   B64= alpha[blank 64]   (s=128, meaningful on lane 31 only)
// Recurrence (p' = p + eps), tp = (lane j-1's Lb) * corr:
//   nLa = (La + Ba + sa*tp) * p'[lab2j]
//   nLb = (Lb + Bb + sb*La) * p'[lab2j+1]
//   nBa = (Ba + tp) * p'[blank]
//   nBb = (Bb + La) * p'[blank]
//   nB64= (B64 + Lb) * p'[blank]
// corr = 2^(off[j-1]-off[j]) is constant between renorms (offsets only change
// at renorm), so it's one extra FMUL in the step. Lane 0 uses corr=0.
// Per-lane scaling keeps every lane's lineage representable in fp32 even when
// lanes differ by hundreds of nats (the global-sum renorm of R1 truncated
// final-state lineages that sat >87 nats below the running total).
//
// Init: pre-alpha = e_0 on blank[0] (Ba lane0 = 1); 512 uniform steps then
// reproduce the reference exactly (the t=0 init falls out of the first step).

#define B_  256
#define T_  512
#define V_  256
#define L_  64
#define CH  8
#define NCH (T_ / CH)
#define EPS 1e-7f
#define FULL 0xFFFFFFFFu
#define MAXGAP 64
#define LN2F 0.6931471805599453f

__global__ void __launch_bounds__(64, 1)
ctc_forward_kernel(const int* __restrict__ y_true,
                   const float* __restrict__ y_pred,
                   float* __restrict__ out)
{
    const int warp = blockIdx.x * (blockDim.x >> 5) + (threadIdx.x >> 5);
    const int lane = threadIdx.x & 31;
    if (warp >= B_) return;

    // Per-lane label pair and skip flags
    const int* lrow = y_true + warp * L_;
    const int la = lrow[2 * lane];
    const int lb = lrow[2 * lane + 1];
    const int lprev = __shfl_up_sync(FULL, lb, 1);  // label[2j-1]; lane0 unused
    const float sa = (la != lprev) ? 1.0f : 0.0f;   // lane0 value irrelevant (tp=0)
    const float sb = (lb != la) ? 1.0f : 0.0f;

    const float* base = y_pred + (size_t)warp * (size_t)(T_ * V_);

    // DP state + per-lane scale
    float La = 0.0f, Lb_s = 0.0f, Ba = (lane == 0) ? 1.0f : 0.0f, Bb = 0.0f, B64 = 0.0f;
    int   off  = 0;                               // lane's log2 scale offset
    float corr = (lane == 0) ? 0.0f : 1.0f;       // 2^(off[j-1]-off[j])

    // Double-buffered prob prefetch
    float Apa[CH], Apb[CH], Apq[CH];
    float Bpa[CH], Bpb[CH], Bpq[CH];

#define LOAD_CHUNK(pa, pb, pq, t0)                                  \
    do {                                                            \
        const float* _r = base + (size_t)(t0) * V_;                 \
        _Pragma("unroll")                                           \
        for (int _i = 0; _i < CH; ++_i) {                           \
            pa[_i] = __ldcs(_r + (size_t)_i * V_ + la);             \
            pb[_i] = __ldcs(_r + (size_t)_i * V_ + lb);             \
            pq[_i] = __ldcs(_r + (size_t)_i * V_ + (V_ - 1));       \
        }                                                           \
    } while (0)

#define STEP(pa_, pb_, pq_)                                         \
    do {                                                            \
        float _pa = (pa_) + EPS;                                    \
        float _pb = (pb_) + EPS;                                    \
        float _pq = (pq_) + EPS;                                    \
        float _tp = __shfl_up_sync(FULL, Lb_s, 1) * corr;           \
        float _nLa = (La + Ba + sa * _tp) * _pa;                    \
        float _nLb = (Lb_s + Bb + sb * La) * _pb;                   \
        float _nBa = (Ba + _tp) * _pq;                              \
        float _nBb = (Bb + La) * _pq;                               \
        float _nB6 = (B64 + Lb_s) * _pq;                            \
        La = _nLa; Lb_s = _nLb; Ba = _nBa; Bb = _nBb; B64 = _nB6;   \
    } while (0)

    // Per-lane renorm: exact power-of-2 rescale, integer offset bookkeeping.
#define RENORM()                                                            \
    do {                                                                    \
        float _m = fmaxf(fmaxf(fmaxf(La, Lb_s), fmaxf(Ba, Bb)), B64);       \
        bool _dead = (_m <= 0.0f);                                          \
        int _iexp = _dead ? 0 : (((__float_as_int(_m) >> 23) & 255) - 127); \
        if (_iexp < -120) _iexp = -120;                                     \
        int _offnew = off + _iexp;                                          \
        int _up = __shfl_up_sync(FULL, _offnew, 1);                         \
        int _offfin;                                                        \
        if (lane == 0)      _offfin = _offnew;                              \
        else if (_dead)     _offfin = _up;     /* adopt upstream scale */   \
        else                _offfin = (_up - MAXGAP > _offnew)              \
                                        ? (_up - MAXGAP) : _offnew;         \
        if (!_dead) {                                                       \
            float _f = ldexpf(1.0f, off - _offfin);                         \
            La *= _f; Lb_s *= _f; Ba *= _f; Bb *= _f; B64 *= _f;            \
        }                                                                   \
        off = _offfin;                                                      \
        int _upf = __shfl_up_sync(FULL, _offfin, 1);                        \
        int _dd = _upf - _offfin;                                           \
        if (_dd > 100) _dd = 100;                                           \
        corr = (lane == 0) ? 0.0f : ldexpf(1.0f, _dd);                      \
    } while (0)

    LOAD_CHUNK(Apa, Apb, Apq, 0);

    for (int c = 0; c < NCH; c += 2) {
        // prefetch chunk c+1 while processing chunk c
        LOAD_CHUNK(Bpa, Bpb, Bpq, (c + 1) * CH);
#pragma unroll
        for (int i = 0; i < CH; ++i) STEP(Apa[i], Apb[i], Apq[i]);
        RENORM();

        if (c + 2 < NCH) LOAD_CHUNK(Apa, Apb, Apq, (c + 2) * CH);
#pragma unroll
        for (int i = 0; i < CH; ++i) STEP(Bpa[i], Bpb[i], Bpq[i]);
        RENORM();
    }

    // final: alpha[S-1] = blank[64] (lane31 B64), alpha[S-2] = label[63] (lane31 Lb)
    if (lane == 31) {
        float v = B64 + Lb_s;                      // scaled by 2^(-off)
        out[warp] = -((__log2f(v) + (float)off) * LN2F);
    }
}

extern "C" void kernel_launch(void* const* d_in, const int* in_sizes, int n_in,
                              void* d_out, int out_size)
{
    // Identify inputs by element count: y_true is B*L int32, y_pred is B*T*V f32
    const int* y_true = nullptr;
    const float* y_pred = nullptr;
    if (in_sizes[0] == B_ * L_) {
        y_true = (const int*)d_in[0];
        y_pred = (const float*)d_in[1];
    } else {
        y_true = (const int*)d_in[1];
        y_pred = (const float*)d_in[0];
    }
    float* out = (float*)d_out;

    // 256 warps total: one warp per batch element, 2 warps/block -> single wave
    dim3 block(64);
    dim3 grid((B_ * 32 + 63) / 64);   // 128 blocks
    ctc_forward_kernel<<<grid, block>>>(y_true, y_pred, out);
}

// round 4
// speedup vs baseline: 1.2721x; 1.2721x over previous
#include <cuda_runtime.h>
#include <cstddef>
#include <cstdint>
#include <math.h>

// CTC batch cost (Keras semantics): B=256, T=512, V=256, L=64, blank=V-1
// loss[b] = -log P(y_true[b] | y_pred[b]), logp = log(y_pred + 1e-7)
//
// Linear-domain forward DP with PER-LANE power-of-2 scaling (exact integer
// exponent offsets, renormalized every 8 steps). One warp per batch element.
// Lane j owns states:
//   La = alpha[label 2j]   (s=4j+1)
//   Lb = alpha[label 2j+1] (s=4j+3)
//   Ba = alpha[blank 2j]   (s=4j)
//   Bb = alpha[blank 2j+1] (s=4j+2)
//   B64= alpha[blank 64]   (s=128, meaningful on lane 31 only)
// Recurrence (p' = p + eps), tp = (lane j-1's Lb) * corr:
//   nLa = (La + Ba + sa*tp) * p'[lab2j]
//   nLb = (Lb + Bb + sb*La) * p'[lab2j+1]
//   nBa = (Ba + tp) * p'[blank]
//   nBb = (Bb + La) * p'[blank]
//   nB64= (B64 + Lb) * p'[blank]
// corr = 2^(off[j-1]-off[j]) is constant between renorms.
//
// R3 change vs R2: 4-buffer register pipeline, prefetch 3 chunks ahead
// (R2 was depth-1; ncu showed latency-bound: dram 38%, occ 3.1%, issue 15%).
// Also: ldexpf -> saturating bit-trick exp2i in the renorm.

#define B_  256
#define T_  512
#define V_  256
#define L_  64
#define CH  8
#define NCH (T_ / CH)
#define EPS 1e-7f
#define FULL 0xFFFFFFFFu
#define MAXGAP 64
#define LN2F 0.6931471805599453f

// 2^e for integer e, saturating: e <= -127 -> 0, e >= 128 -> +inf-ish (2^127)
__device__ __forceinline__ float exp2i(int e)
{
    if (e <= -127) return 0.0f;
    if (e > 127)   e = 127;
    return __int_as_float((e + 127) << 23);
}

__global__ void __launch_bounds__(64, 1)
ctc_forward_kernel(const int* __restrict__ y_true,
                   const float* __restrict__ y_pred,
                   float* __restrict__ out)
{
    const int warp = blockIdx.x * (blockDim.x >> 5) + (threadIdx.x >> 5);
    const int lane = threadIdx.x & 31;
    if (warp >= B_) return;

    // Per-lane label pair and skip flags
    const int* lrow = y_true + warp * L_;
    const int la = lrow[2 * lane];
    const int lb = lrow[2 * lane + 1];
    const int lprev = __shfl_up_sync(FULL, lb, 1);  // label[2j-1]; lane0 unused
    const float sa = (la != lprev) ? 1.0f : 0.0f;   // lane0 value irrelevant (tp=0)
    const float sb = (lb != la) ? 1.0f : 0.0f;

    const float* base = y_pred + (size_t)warp * (size_t)(T_ * V_);

    // DP state + per-lane scale
    float La = 0.0f, Lb_s = 0.0f, Ba = (lane == 0) ? 1.0f : 0.0f, Bb = 0.0f, B64 = 0.0f;
    int   off  = 0;                               // lane's log2 scale offset
    float corr = (lane == 0) ? 0.0f : 1.0f;       // 2^(off[j-1]-off[j])

    // 4 rotating prefetch buffers (depth-3 pipeline)
    float P0a[CH], P0b[CH], P0q[CH];
    float P1a[CH], P1b[CH], P1q[CH];
    float P2a[CH], P2b[CH], P2q[CH];
    float P3a[CH], P3b[CH], P3q[CH];

#define LOAD_CHUNK(pa, pb, pq, t0)                                  \
    do {                                                            \
        const float* _r = base + (size_t)(t0) * V_;                 \
        _Pragma("unroll")                                           \
        for (int _i = 0; _i < CH; ++_i) {                           \
            pa[_i] = __ldcs(_r + (size_t)_i * V_ + la);             \
            pb[_i] = __ldcs(_r + (size_t)_i * V_ + lb);             \
            pq[_i] = __ldcs(_r + (size_t)_i * V_ + (V_ - 1));       \
        }                                                           \
    } while (0)

#define STEP(pa_, pb_, pq_)                                         \
    do {                                                            \
        float _pa = (pa_) + EPS;                                    \
        float _pb = (pb_) + EPS;                                    \
        float _pq = (pq_) + EPS;                                    \
        float _tp = __shfl_up_sync(FULL, Lb_s, 1) * corr;           \
        float _nLa = (La + Ba + sa * _tp) * _pa;                    \
        float _nLb = (Lb_s + Bb + sb * La) * _pb;                   \
        float _nBa = (Ba + _tp) * _pq;                              \
        float _nBb = (Bb + La) * _pq;                               \
        float _nB6 = (B64 + Lb_s) * _pq;                            \
        La = _nLa; Lb_s = _nLb; Ba = _nBa; Bb = _nBb; B64 = _nB6;   \
    } while (0)

    // Per-lane renorm: exact power-of-2 rescale, integer offset bookkeeping.
#define RENORM()                                                            \
    do {                                                                    \
        float _m = fmaxf(fmaxf(fmaxf(La, Lb_s), fmaxf(Ba, Bb)), B64);       \
        bool _dead = (_m <= 0.0f);                                          \
        int _iexp = _dead ? 0 : (((__float_as_int(_m) >> 23) & 255) - 127); \
        if (_iexp < -120) _iexp = -120;                                     \
        int _offnew = off + _iexp;                                          \
        int _up = __shfl_up_sync(FULL, _offnew, 1);                         \
        int _offfin;                                                        \
        if (lane == 0)      _offfin = _offnew;                              \
        else if (_dead)     _offfin = _up;     /* adopt upstream scale */   \
        else                _offfin = (_up - MAXGAP > _offnew)              \
                                        ? (_up - MAXGAP) : _offnew;         \
        if (!_dead) {                                                       \
            float _f = exp2i(off - _offfin);                                \
            La *= _f; Lb_s *= _f; Ba *= _f; Bb *= _f; B64 *= _f;            \
        }                                                                   \
        off = _offfin;                                                      \
        int _upf = __shfl_up_sync(FULL, _offfin, 1);                        \
        int _dd = _upf - _offfin;                                           \
        if (_dd > 100) _dd = 100;                                           \
        corr = (lane == 0) ? 0.0f : exp2i(_dd);                             \
    } while (0)

#define PROC(pa, pb, pq)                                            \
    do {                                                            \
        _Pragma("unroll")                                           \
        for (int _s = 0; _s < CH; ++_s) STEP(pa[_s], pb[_s], pq[_s]); \
        RENORM();                                                   \
    } while (0)

    // Prime the pipeline: 3 chunks in flight
    LOAD_CHUNK(P0a, P0b, P0q, 0 * CH);
    LOAD_CHUNK(P1a, P1b, P1q, 1 * CH);
    LOAD_CHUNK(P2a, P2b, P2q, 2 * CH);

    for (int c = 0; c < NCH; c += 4) {
        if (c + 3 < NCH) LOAD_CHUNK(P3a, P3b, P3q, (c + 3) * CH);
        PROC(P0a, P0b, P0q);

        if (c + 4 < NCH) LOAD_CHUNK(P0a, P0b, P0q, (c + 4) * CH);
        PROC(P1a, P1b, P1q);

        if (c + 5 < NCH) LOAD_CHUNK(P1a, P1b, P1q, (c + 5) * CH);
        PROC(P2a, P2b, P2q);

        if (c + 6 < NCH) LOAD_CHUNK(P2a, P2b, P2q, (c + 6) * CH);
        PROC(P3a, P3b, P3q);
    }

    // final: alpha[S-1] = blank[64] (lane31 B64), alpha[S-2] = label[63] (lane31 Lb)
    if (lane == 31) {
        float v = B64 + Lb_s;                      // scaled by 2^off
        out[warp] = -((__log2f(v) + (float)off) * LN2F);
    }
}

extern "C" void kernel_launch(void* const* d_in, const int* in_sizes, int n_in,
                              void* d_out, int out_size)
{
    // Identify inputs by element count: y_true is B*L int32, y_pred is B*T*V f32
    const int* y_true = nullptr;
    const float* y_pred = nullptr;
    if (in_sizes[0] == B_ * L_) {
        y_true = (const int*)d_in[0];
        y_pred = (const float*)d_in[1];
    } else {
        y_true = (const int*)d_in[1];
        y_pred = (const float*)d_in[0];
    }
    float* out = (float*)d_out;

    // 256 warps total: one warp per batch element, 2 warps/block -> single wave
    dim3 block(64);
    dim3 grid((B_ * 32 + 63) / 64);   // 128 blocks
    ctc_forward_kernel<<<grid, block>>>(y_true, y_pred, out);
}